// round 7
// baseline (speedup 1.0000x reference)
#include <cuda_runtime.h>
#include <cstdint>

#define NROW   8192
#define DIM    64
#define KTOT   128
#define BM     64
#define BN     256
#define KC     16
#define NTHR   256
#define NTILES (NROW / BN)      // 32
#define NCHUNK (KTOT / KC)      // 8
#define TOPK   32

// scratch: U = [nv1|nv2] k-major, V = [nv2|-nv1] k-major
__device__ float Ug[KTOT * NROW];
__device__ float Vg[KTOT * NROW];

// XLA EmitFastTanh / Eigen generic_fast_tanh_float, with_fma = true:
// clamp +/-7.99881172180175781 (the FMA-variant clamp), Horner via fused
// multiply-add, final numerator multiply separate, IEEE div, small-x pass.
__device__ __forceinline__ float xla_tanh(float x) {
    const float kClamp = 7.99881172180175781f;
    float ax = fabsf(x);
    float xc = fminf(fmaxf(x, -kClamp), kClamp);
    float x2 = __fmul_rn(xc, xc);
    float num = -2.76076847742355e-16f;
    num = fmaf(x2, num, 2.00018790482477e-13f);
    num = fmaf(x2, num, -8.60467152213735e-11f);
    num = fmaf(x2, num, 5.12229709037114e-08f);
    num = fmaf(x2, num, 1.48572235717979e-05f);
    num = fmaf(x2, num, 6.37261928875436e-04f);
    num = fmaf(x2, num, 4.89352455891786e-03f);
    num = __fmul_rn(xc, num);
    float den = 1.19825839466702e-06f;
    den = fmaf(x2, den, 1.18534705686654e-04f);
    den = fmaf(x2, den, 2.26843463243900e-03f);
    den = fmaf(x2, den, 4.89352518554385e-03f);
    float r = __fdiv_rn(num, den);
    return (ax < 0.0004f) ? x : r;
}

// ---------------- kernel A: build U, V (k-major) ----------------
__global__ void __launch_bounds__(256) prep_kernel(
    const int* __restrict__ idx,
    const float* __restrict__ emb1, const float* __restrict__ emb2,
    const float* __restrict__ W1, const float* __restrict__ b1,
    const float* __restrict__ W2, const float* __restrict__ b2)
{
    __shared__ float W1s[64][65], W2s[64][65];
    __shared__ float b1s[64], b2s[64];
    __shared__ float e1s[4][64], e2s[4][64];
    int tid = threadIdx.x;
    for (int i = tid; i < 64 * 64; i += 256) {
        int o = i >> 6, d = i & 63;
        W1s[o][d] = W1[i];
        W2s[o][d] = W2[i];
    }
    if (tid < 64) { b1s[tid] = b1[tid]; b2s[tid] = b2[tid]; }
    int rb  = tid >> 6;           // 0..3 row within block
    int o   = tid & 63;           // output feature
    int row = blockIdx.x * 4 + rb;
    int g   = idx[row];
    e1s[rb][o] = emb1[(size_t)g * 64 + o];
    e2s[rb][o] = emb2[(size_t)g * 64 + o];
    __syncthreads();
    float d1 = 0.f, d2 = 0.f;
#pragma unroll
    for (int d = 0; d < 64; d++) {
        d1 = fmaf(e1s[rb][d], W1s[o][d], d1);
        d2 = fmaf(e2s[rb][d], W2s[o][d], d2);
    }
    float nv1 = xla_tanh(__fmul_rn(3.0f, __fadd_rn(d1, b1s[o])));
    float nv2 = xla_tanh(__fmul_rn(3.0f, __fadd_rn(d2, b2s[o])));
    Ug[(size_t)o * NROW + row]        = nv1;
    Ug[(size_t)(o + 64) * NROW + row] = nv2;
    Vg[(size_t)o * NROW + row]        = nv2;
    Vg[(size_t)(o + 64) * NROW + row] = -nv1;
}

// ---------------- kernel B: GEMM + fused tanh/relu/top-K + write ----------------
#define SM_US 0
#define SM_VS 8192
#define SM_CS 16384
#define SM_KV (16384 + 64 * 260)
#define SM_KJ (SM_KV + 64 * 32)
#define SMEM_FLOATS (SM_KJ + 64 * 32)
#define SMEM_BYTES (SMEM_FLOATS * 4)

__global__ void __launch_bounds__(NTHR, 1) adj_kernel(float* __restrict__ out)
{
    extern __shared__ float sm[];
    float* Us  = sm + SM_US;
    float* Vs  = sm + SM_VS;
    float* Cs  = sm + SM_CS;
    float* kvS = sm + SM_KV;
    int*   kjS = (int*)(sm + SM_KJ);

    int tid = threadIdx.x;
    int r0  = blockIdx.x * BM;

    // zero this block's 64 output rows (overlaps with mainloop)
    {
        float4 z = make_float4(0.f, 0.f, 0.f, 0.f);
        float4* ov = (float4*)(out + (size_t)r0 * NROW);
        for (int i = tid; i < BM * NROW / 4; i += NTHR) ov[i] = z;
    }

    // load resident U tile [128][64]
#pragma unroll
    for (int i = 0; i < 8; i++) {
        int f  = tid + NTHR * i;           // 0..2047 float4s
        int k  = f >> 4;
        int m4 = (f & 15) << 2;
        *(float4*)&Us[k * 64 + m4] = *(const float4*)&Ug[(size_t)k * NROW + r0 + m4];
    }

    // thread micro-tile mapping
    int tx  = tid & 31, ty = tid >> 5;
    int rm0 = ty * 4, rm1 = 32 + ty * 4;
    int cn0 = tx * 4, cn1 = 128 + tx * 4;

    // per-row top-K state (owner threads tid < 64)
    float thv  = 0.f;       // min kept v (valid once cnt==32)
    float thaM = 0.f;       // raw-a reject threshold (monotone prefilter)
    int   cnt  = 0;

    // chunk prefetch registers
    float4 pf0, pf1, pf2, pf3;
    int pk0, pn0, pk1, pn1, pk2, pn2, pk3, pn3;

    // prefetch chunk 0 of tile 0
    {
        int f;
        f = tid;             pk0 = f >> 6; pn0 = (f & 63) << 2;
        f = tid + NTHR;      pk1 = f >> 6; pn1 = (f & 63) << 2;
        f = tid + 2 * NTHR;  pk2 = f >> 6; pn2 = (f & 63) << 2;
        f = tid + 3 * NTHR;  pk3 = f >> 6; pn3 = (f & 63) << 2;
        pf0 = *(const float4*)&Vg[(size_t)pk0 * NROW + pn0];
        pf1 = *(const float4*)&Vg[(size_t)pk1 * NROW + pn1];
        pf2 = *(const float4*)&Vg[(size_t)pk2 * NROW + pn2];
        pf3 = *(const float4*)&Vg[(size_t)pk3 * NROW + pn3];
        *(float4*)&Vs[pk0 * BN + pn0] = pf0;
        *(float4*)&Vs[pk1 * BN + pn1] = pf1;
        *(float4*)&Vs[pk2 * BN + pn2] = pf2;
        *(float4*)&Vs[pk3 * BN + pn3] = pf3;
    }
    __syncthreads();

    int cur = 0;
    for (int jt = 0; jt < NTILES; jt++) {
        float acc[8][8];
#pragma unroll
        for (int i = 0; i < 8; i++)
#pragma unroll
            for (int j = 0; j < 8; j++) acc[i][j] = 0.f;

        for (int kc = 0; kc < NCHUNK; kc++) {
            int g = jt * NCHUNK + kc + 1;   // next global chunk id
            bool more = (g < NTILES * NCHUNK);
            if (more) {
                int njt = g >> 3, nkc = g & 7;
                size_t base = (size_t)(nkc * KC) * NROW + njt * BN;
                pf0 = *(const float4*)&Vg[base + (size_t)pk0 * NROW + pn0];
                pf1 = *(const float4*)&Vg[base + (size_t)pk1 * NROW + pn1];
                pf2 = *(const float4*)&Vg[base + (size_t)pk2 * NROW + pn2];
                pf3 = *(const float4*)&Vg[base + (size_t)pk3 * NROW + pn3];
            }
            const float* vb = Vs + cur * (KC * BN);
            const float* ub = Us + kc * KC * 64;
#pragma unroll
            for (int k = 0; k < KC; k++) {
                float4 a0 = *(const float4*)&ub[k * 64 + rm0];
                float4 a1 = *(const float4*)&ub[k * 64 + rm1];
                float4 b0 = *(const float4*)&vb[k * BN + cn0];
                float4 b1 = *(const float4*)&vb[k * BN + cn1];
                float av[8] = {a0.x, a0.y, a0.z, a0.w, a1.x, a1.y, a1.z, a1.w};
                float bv[8] = {b0.x, b0.y, b0.z, b0.w, b1.x, b1.y, b1.z, b1.w};
#pragma unroll
                for (int i = 0; i < 8; i++)
#pragma unroll
                    for (int j = 0; j < 8; j++)
                        acc[i][j] = fmaf(av[i], bv[j], acc[i][j]);
            }
            if (more) {
                float* vw = Vs + (cur ^ 1) * (KC * BN);
                *(float4*)&vw[pk0 * BN + pn0] = pf0;
                *(float4*)&vw[pk1 * BN + pn1] = pf1;
                *(float4*)&vw[pk2 * BN + pn2] = pf2;
                *(float4*)&vw[pk3 * BN + pn3] = pf3;
            }
            __syncthreads();
            cur ^= 1;
        }

        // stage C tile to smem
#pragma unroll
        for (int i = 0; i < 8; i++) {
            int r = (i < 4) ? (rm0 + i) : (rm1 + i - 4);
            *(float4*)&Cs[r * 260 + cn0] = *(float4*)&acc[i][0];
            *(float4*)&Cs[r * 260 + cn1] = *(float4*)&acc[i][4];
        }
        __syncthreads();

        // owner threads scan their row
        if (tid < 64) {
            int jbase = jt * BN;
            const float* crow = &Cs[tid * 260];
#pragma unroll 4
            for (int c4 = 0; c4 < BN / 4; c4++) {
                float4 q = *(const float4*)&crow[c4 * 4];
                float vals[4] = {q.x, q.y, q.z, q.w};
#pragma unroll
                for (int e = 0; e < 4; e++) {
                    float a = vals[e];
                    if (a <= thaM) continue;          // monotone prefilter
                    float v = xla_tanh(__fmul_rn(3.0f, a));
                    int jidx = jbase + c4 * 4 + e;
                    if (cnt < TOPK) {
                        kvS[tid * TOPK + cnt] = v;
                        kjS[tid * TOPK + cnt] = jidx;
                        cnt++;
                        if (cnt == TOPK) {
                            float mv = kvS[tid * TOPK];
                            for (int s = 1; s < TOPK; s++) mv = fminf(mv, kvS[tid * TOPK + s]);
                            thv = mv;
                        }
                    } else if (v > thv) {
                        // evict worst: min v, tie -> largest index
                        int ms = 0; float mv = kvS[tid * TOPK]; int mj = kjS[tid * TOPK];
                        for (int s = 1; s < TOPK; s++) {
                            float sv = kvS[tid * TOPK + s]; int sj = kjS[tid * TOPK + s];
                            if (sv < mv || (sv == mv && sj > mj)) { ms = s; mv = sv; mj = sj; }
                        }
                        kvS[tid * TOPK + ms] = v;
                        kjS[tid * TOPK + ms] = jidx;
                        float nm = kvS[tid * TOPK];
                        for (int s = 1; s < TOPK; s++) nm = fminf(nm, kvS[tid * TOPK + s]);
                        thv = nm;
                    } else {
                        // confirmed reject: raise raw-a threshold (monotone in a)
                        thaM = fmaxf(thaM, a);
                    }
                }
            }
        }
        __syncthreads();
    }

    // scatter kept values into zeroed output rows
    if (tid < 64) {
        float* orow = out + (size_t)(r0 + tid) * NROW;
        for (int s = 0; s < cnt; s++) {
            orow[kjS[tid * TOPK + s]] = kvS[tid * TOPK + s];
        }
    }
}

extern "C" void kernel_launch(void* const* d_in, const int* in_sizes, int n_in,
                              void* d_out, int out_size)
{
    const int*   idx  = (const int*)d_in[0];
    const float* emb1 = (const float*)d_in[1];
    const float* emb2 = (const float*)d_in[2];
    const float* W1   = (const float*)d_in[3];
    const float* b1   = (const float*)d_in[4];
    const float* W2   = (const float*)d_in[5];
    const float* b2   = (const float*)d_in[6];
    float* out = (float*)d_out;

    static bool configured = false;
    if (!configured) {
        cudaFuncSetAttribute(adj_kernel, cudaFuncAttributeMaxDynamicSharedMemorySize, SMEM_BYTES);
        configured = true;
    }

    prep_kernel<<<NROW / 4, 256>>>(idx, emb1, emb2, W1, b1, W2, b2);
    adj_kernel<<<NROW / BM, NTHR, SMEM_BYTES>>>(out);
}

// round 8
// speedup vs baseline: 3.7787x; 3.7787x over previous
#include <cuda_runtime.h>
#include <cstdint>

#define NROW   8192
#define DIM    64
#define KTOT   128
#define BM     64
#define BN     256
#define KC     16
#define NTHR   256
#define NCHUNK (KTOT / KC)      // 8
#define TOPK   32
#define NTILES_S1 2             // stage 1 covers columns 0..511
#define FB_ROWS 32              // rows per fallback CTA

// scratch: U = [nv1|nv2] k-major, V = [nv2|-nv1] k-major
__device__ float Ug[KTOT * NROW];
__device__ float Vg[KTOT * NROW];
__device__ int   g_unf[NROW];   // 1 = row needs fallback

// XLA EmitFastTanh / Eigen generic_fast_tanh_float, with_fma = true:
// clamp +/-7.99881172180175781, fmaf Horner, final mul separate, IEEE div.
__device__ __forceinline__ float xla_tanh(float x) {
    const float kClamp = 7.99881172180175781f;
    float ax = fabsf(x);
    float xc = fminf(fmaxf(x, -kClamp), kClamp);
    float x2 = __fmul_rn(xc, xc);
    float num = -2.76076847742355e-16f;
    num = fmaf(x2, num, 2.00018790482477e-13f);
    num = fmaf(x2, num, -8.60467152213735e-11f);
    num = fmaf(x2, num, 5.12229709037114e-08f);
    num = fmaf(x2, num, 1.48572235717979e-05f);
    num = fmaf(x2, num, 6.37261928875436e-04f);
    num = fmaf(x2, num, 4.89352455891786e-03f);
    num = __fmul_rn(xc, num);
    float den = 1.19825839466702e-06f;
    den = fmaf(x2, den, 1.18534705686654e-04f);
    den = fmaf(x2, den, 2.26843463243900e-03f);
    den = fmaf(x2, den, 4.89352518554385e-03f);
    float r = __fdiv_rn(num, den);
    return (ax < 0.0004f) ? x : r;
}

// ---------------- kernel A: build U, V (k-major) ----------------
__global__ void __launch_bounds__(256) prep_kernel(
    const int* __restrict__ idx,
    const float* __restrict__ emb1, const float* __restrict__ emb2,
    const float* __restrict__ W1, const float* __restrict__ b1,
    const float* __restrict__ W2, const float* __restrict__ b2)
{
    __shared__ float W1s[64][65], W2s[64][65];
    __shared__ float b1s[64], b2s[64];
    __shared__ float e1s[4][64], e2s[4][64];
    int tid = threadIdx.x;
    for (int i = tid; i < 64 * 64; i += 256) {
        int o = i >> 6, d = i & 63;
        W1s[o][d] = W1[i];
        W2s[o][d] = W2[i];
    }
    if (tid < 64) { b1s[tid] = b1[tid]; b2s[tid] = b2[tid]; }
    int rb  = tid >> 6;
    int o   = tid & 63;
    int row = blockIdx.x * 4 + rb;
    int g   = idx[row];
    e1s[rb][o] = emb1[(size_t)g * 64 + o];
    e2s[rb][o] = emb2[(size_t)g * 64 + o];
    __syncthreads();
    float d1 = 0.f, d2 = 0.f;
#pragma unroll
    for (int d = 0; d < 64; d++) {
        d1 = fmaf(e1s[rb][d], W1s[o][d], d1);
        d2 = fmaf(e2s[rb][d], W2s[o][d], d2);
    }
    float nv1 = xla_tanh(__fmul_rn(3.0f, __fadd_rn(d1, b1s[o])));
    float nv2 = xla_tanh(__fmul_rn(3.0f, __fadd_rn(d2, b2s[o])));
    Ug[(size_t)o * NROW + row]        = nv1;
    Ug[(size_t)(o + 64) * NROW + row] = nv2;
    Vg[(size_t)o * NROW + row]        = nv2;
    Vg[(size_t)(o + 64) * NROW + row] = -nv1;
}

// ---------------- kernel B: stage-1 GEMM (cols 0..511) + top-K ----------------
#define SM_US 0
#define SM_VS 8192
#define SM_CS 16384
#define SM_KV (16384 + 64 * 260)
#define SM_KJ (SM_KV + 64 * 32)
#define SMEM_FLOATS (SM_KJ + 64 * 32)
#define SMEM_BYTES (SMEM_FLOATS * 4)

__global__ void __launch_bounds__(NTHR, 1) stage1_kernel(float* __restrict__ out)
{
    extern __shared__ float sm[];
    float* Us  = sm + SM_US;
    float* Vs  = sm + SM_VS;
    float* Cs  = sm + SM_CS;
    float* kvS = sm + SM_KV;
    int*   kjS = (int*)(sm + SM_KJ);

    int tid = threadIdx.x;
    int r0  = blockIdx.x * BM;

    // zero this block's 64 output rows (overlaps with mainloop)
    {
        float4 z = make_float4(0.f, 0.f, 0.f, 0.f);
        float4* ov = (float4*)(out + (size_t)r0 * NROW);
        for (int i = tid; i < BM * NROW / 4; i += NTHR) ov[i] = z;
    }

    // load resident U tile [128][64]
#pragma unroll
    for (int i = 0; i < 8; i++) {
        int f  = tid + NTHR * i;
        int k  = f >> 4;
        int m4 = (f & 15) << 2;
        *(float4*)&Us[k * 64 + m4] = *(const float4*)&Ug[(size_t)k * NROW + r0 + m4];
    }

    int tx  = tid & 31, ty = tid >> 5;
    int rm0 = ty * 4, rm1 = 32 + ty * 4;
    int cn0 = tx * 4, cn1 = 128 + tx * 4;

    float thv  = 0.f;
    float thaM = 0.f;
    int   cnt  = 0;

    float4 pf0, pf1, pf2, pf3;
    int pk0, pn0, pk1, pn1, pk2, pn2, pk3, pn3;

    {
        int f;
        f = tid;             pk0 = f >> 6; pn0 = (f & 63) << 2;
        f = tid + NTHR;      pk1 = f >> 6; pn1 = (f & 63) << 2;
        f = tid + 2 * NTHR;  pk2 = f >> 6; pn2 = (f & 63) << 2;
        f = tid + 3 * NTHR;  pk3 = f >> 6; pn3 = (f & 63) << 2;
        pf0 = *(const float4*)&Vg[(size_t)pk0 * NROW + pn0];
        pf1 = *(const float4*)&Vg[(size_t)pk1 * NROW + pn1];
        pf2 = *(const float4*)&Vg[(size_t)pk2 * NROW + pn2];
        pf3 = *(const float4*)&Vg[(size_t)pk3 * NROW + pn3];
        *(float4*)&Vs[pk0 * BN + pn0] = pf0;
        *(float4*)&Vs[pk1 * BN + pn1] = pf1;
        *(float4*)&Vs[pk2 * BN + pn2] = pf2;
        *(float4*)&Vs[pk3 * BN + pn3] = pf3;
    }
    __syncthreads();

    int cur = 0;
    for (int jt = 0; jt < NTILES_S1; jt++) {
        float acc[8][8];
#pragma unroll
        for (int i = 0; i < 8; i++)
#pragma unroll
            for (int j = 0; j < 8; j++) acc[i][j] = 0.f;

        for (int kc = 0; kc < NCHUNK; kc++) {
            int g = jt * NCHUNK + kc + 1;
            bool more = (g < NTILES_S1 * NCHUNK);
            if (more) {
                int njt = g >> 3, nkc = g & 7;
                size_t base = (size_t)(nkc * KC) * NROW + njt * BN;
                pf0 = *(const float4*)&Vg[base + (size_t)pk0 * NROW + pn0];
                pf1 = *(const float4*)&Vg[base + (size_t)pk1 * NROW + pn1];
                pf2 = *(const float4*)&Vg[base + (size_t)pk2 * NROW + pn2];
                pf3 = *(const float4*)&Vg[base + (size_t)pk3 * NROW + pn3];
            }
            const float* vb = Vs + cur * (KC * BN);
            const float* ub = Us + kc * KC * 64;
#pragma unroll
            for (int k = 0; k < KC; k++) {
                float4 a0 = *(const float4*)&ub[k * 64 + rm0];
                float4 a1 = *(const float4*)&ub[k * 64 + rm1];
                float4 b0 = *(const float4*)&vb[k * BN + cn0];
                float4 b1 = *(const float4*)&vb[k * BN + cn1];
                float av[8] = {a0.x, a0.y, a0.z, a0.w, a1.x, a1.y, a1.z, a1.w};
                float bv[8] = {b0.x, b0.y, b0.z, b0.w, b1.x, b1.y, b1.z, b1.w};
#pragma unroll
                for (int i = 0; i < 8; i++)
#pragma unroll
                    for (int j = 0; j < 8; j++)
                        acc[i][j] = fmaf(av[i], bv[j], acc[i][j]);
            }
            if (more) {
                float* vw = Vs + (cur ^ 1) * (KC * BN);
                *(float4*)&vw[pk0 * BN + pn0] = pf0;
                *(float4*)&vw[pk1 * BN + pn1] = pf1;
                *(float4*)&vw[pk2 * BN + pn2] = pf2;
                *(float4*)&vw[pk3 * BN + pn3] = pf3;
            }
            __syncthreads();
            cur ^= 1;
        }

        // stage C tile to smem
#pragma unroll
        for (int i = 0; i < 8; i++) {
            int r = (i < 4) ? (rm0 + i) : (rm1 + i - 4);
            *(float4*)&Cs[r * 260 + cn0] = *(float4*)&acc[i][0];
            *(float4*)&Cs[r * 260 + cn1] = *(float4*)&acc[i][4];
        }
        __syncthreads();

        // owner threads scan their row (index-ascending)
        if (tid < 64) {
            int jbase = jt * BN;
            const float* crow = &Cs[tid * 260];
#pragma unroll 4
            for (int c4 = 0; c4 < BN / 4; c4++) {
                float4 q = *(const float4*)&crow[c4 * 4];
                float vals[4] = {q.x, q.y, q.z, q.w};
#pragma unroll
                for (int e = 0; e < 4; e++) {
                    float a = vals[e];
                    if (a <= thaM) continue;
                    float v = xla_tanh(__fmul_rn(3.0f, a));
                    int jidx = jbase + c4 * 4 + e;
                    if (cnt < TOPK) {
                        kvS[tid * TOPK + cnt] = v;
                        kjS[tid * TOPK + cnt] = jidx;
                        cnt++;
                        if (cnt == TOPK) {
                            float mv = kvS[tid * TOPK];
                            for (int s = 1; s < TOPK; s++) mv = fminf(mv, kvS[tid * TOPK + s]);
                            thv = mv;
                        }
                    } else if (v > thv) {
                        int ms = 0; float mv = kvS[tid * TOPK]; int mj = kjS[tid * TOPK];
                        for (int s = 1; s < TOPK; s++) {
                            float sv = kvS[tid * TOPK + s]; int sj = kjS[tid * TOPK + s];
                            if (sv < mv || (sv == mv && sj > mj)) { ms = s; mv = sv; mj = sj; }
                        }
                        kvS[tid * TOPK + ms] = v;
                        kjS[tid * TOPK + ms] = jidx;
                        float nm = kvS[tid * TOPK];
                        for (int s = 1; s < TOPK; s++) nm = fminf(nm, kvS[tid * TOPK + s]);
                        thv = nm;
                    } else {
                        thaM = fmaxf(thaM, a);
                    }
                }
            }
        }
        __syncthreads();
    }

    // finished iff all 32 kept are at the saturated plateau: no later column
    // can evict (strictly-greater required; ties lose by index).
    if (tid < 64) {
        const float vmax = xla_tanh(30.0f);
        int row = r0 + tid;
        bool fin = (cnt == TOPK) && (thv >= vmax);
        g_unf[row] = fin ? 0 : 1;
        if (fin) {
            float* orow = out + (size_t)row * NROW;
            for (int s = 0; s < TOPK; s++) {
                orow[kjS[tid * TOPK + s]] = kvS[tid * TOPK + s];
            }
        }
    }
}

// ---------------- kernel C: fallback — full-row top-K for unfinished rows ----
__global__ void __launch_bounds__(256) fallback_kernel(float* __restrict__ out)
{
    __shared__ float us[KTOT];
    __shared__ float as[256];
    __shared__ float kv[TOPK];
    __shared__ int   kj[TOPK];
    __shared__ float s_thv, s_thaM;
    __shared__ int   s_cnt, s_done;

    int tid = threadIdx.x;
    const float vmax = xla_tanh(30.0f);

    for (int rr = 0; rr < FB_ROWS; rr++) {
        int row = blockIdx.x * FB_ROWS + rr;
        if (g_unf[row] == 0) continue;     // uniform across block

        // load u_row (k-major gather)
        if (tid < KTOT) us[tid] = Ug[(size_t)tid * NROW + row];
        if (tid == 0) { s_cnt = 0; s_thv = 0.f; s_thaM = 0.f; s_done = 0; }
        __syncthreads();

        for (int jt = 0; jt < NROW / 256; jt++) {
            int j = jt * 256 + tid;
            float acc = 0.f;
#pragma unroll 16
            for (int k = 0; k < KTOT; k++)
                acc = fmaf(us[k], Vg[(size_t)k * NROW + j], acc);
            as[tid] = acc;
            __syncthreads();

            if (tid == 0) {
                int   cnt  = s_cnt;
                float thv  = s_thv;
                float thaM = s_thaM;
                int jbase = jt * 256;
                for (int c = 0; c < 256; c++) {
                    float a = as[c];
                    if (a <= thaM) continue;
                    float v = xla_tanh(__fmul_rn(3.0f, a));
                    int jidx = jbase + c;
                    if (cnt < TOPK) {
                        kv[cnt] = v; kj[cnt] = jidx; cnt++;
                        if (cnt == TOPK) {
                            float mv = kv[0];
                            for (int s = 1; s < TOPK; s++) mv = fminf(mv, kv[s]);
                            thv = mv;
                        }
                    } else if (v > thv) {
                        int ms = 0; float mv = kv[0]; int mj = kj[0];
                        for (int s = 1; s < TOPK; s++) {
                            if (kv[s] < mv || (kv[s] == mv && kj[s] > mj)) { ms = s; mv = kv[s]; mj = kj[s]; }
                        }
                        kv[ms] = v; kj[ms] = jidx;
                        float nm = kv[0];
                        for (int s = 1; s < TOPK; s++) nm = fminf(nm, kv[s]);
                        thv = nm;
                    } else {
                        thaM = fmaxf(thaM, a);
                    }
                }
                s_cnt = cnt; s_thv = thv; s_thaM = thaM;
                if (cnt == TOPK && thv >= vmax) s_done = 1;
            }
            __syncthreads();
            if (s_done) break;
        }

        if (tid == 0) {
            float* orow = out + (size_t)row * NROW;
            for (int s = 0; s < s_cnt; s++) orow[kj[s]] = kv[s];
        }
        __syncthreads();
    }
}

extern "C" void kernel_launch(void* const* d_in, const int* in_sizes, int n_in,
                              void* d_out, int out_size)
{
    const int*   idx  = (const int*)d_in[0];
    const float* emb1 = (const float*)d_in[1];
    const float* emb2 = (const float*)d_in[2];
    const float* W1   = (const float*)d_in[3];
    const float* b1   = (const float*)d_in[4];
    const float* W2   = (const float*)d_in[5];
    const float* b2   = (const float*)d_in[6];
    float* out = (float*)d_out;

    static bool configured = false;
    if (!configured) {
        cudaFuncSetAttribute(stage1_kernel, cudaFuncAttributeMaxDynamicSharedMemorySize, SMEM_BYTES);
        configured = true;
    }

    prep_kernel<<<NROW / 4, 256>>>(idx, emb1, emb2, W1, b1, W2, b2);
    stage1_kernel<<<NROW / BM, NTHR, SMEM_BYTES>>>(out);
    fallback_kernel<<<NROW / FB_ROWS, 256>>>(out);
}

// round 10
// speedup vs baseline: 4.2799x; 1.1326x over previous
#include <cuda_runtime.h>
#include <cstdint>

#define NROW   8192
#define DIM    64
#define KTOT   128
#define BM     64
#define BN     256
#define KC     16
#define NTHR   256
#define NCHUNK (KTOT / KC)      // 8
#define TOPK   32
#define NTILES_S1 1             // stage 1 covers columns 0..255
#define FB_ROWS 32              // rows per fallback CTA
#define PR_ROWS 16              // rows per prep CTA

// scratch: U = [nv1|nv2] k-major, V = [nv2|-nv1] k-major
__device__ float Ug[KTOT * NROW];
__device__ float Vg[KTOT * NROW];
__device__ int   g_unf[NROW];   // 1 = row needs fallback

// XLA EmitFastTanh / Eigen generic_fast_tanh_float, with_fma = true:
// clamp +/-7.99881172180175781, fmaf Horner, final mul separate, IEEE div.
__device__ __forceinline__ float xla_tanh(float x) {
    const float kClamp = 7.99881172180175781f;
    float ax = fabsf(x);
    float xc = fminf(fmaxf(x, -kClamp), kClamp);
    float x2 = __fmul_rn(xc, xc);
    float num = -2.76076847742355e-16f;
    num = fmaf(x2, num, 2.00018790482477e-13f);
    num = fmaf(x2, num, -8.60467152213735e-11f);
    num = fmaf(x2, num, 5.12229709037114e-08f);
    num = fmaf(x2, num, 1.48572235717979e-05f);
    num = fmaf(x2, num, 6.37261928875436e-04f);
    num = fmaf(x2, num, 4.89352455891786e-03f);
    num = __fmul_rn(xc, num);
    float den = 1.19825839466702e-06f;
    den = fmaf(x2, den, 1.18534705686654e-04f);
    den = fmaf(x2, den, 2.26843463243900e-03f);
    den = fmaf(x2, den, 4.89352518554385e-03f);
    float r = __fdiv_rn(num, den);
    return (ax < 0.0004f) ? x : r;
}

// ---------------- kernel A: build U, V (k-major), coalesced stores ----------
// dynamic smem layout (floats):
//  W1s[64*65]  W2s[64*65]  e1s[16*64]  e2s[16*64]  nv1s[64*17]  nv2s[64*17]
//  b1s[64]  b2s[64]
#define PW1  0
#define PW2  (PW1 + 64 * 65)
#define PE1  (PW2 + 64 * 65)
#define PE2  (PE1 + PR_ROWS * 64)
#define PN1  (PE2 + PR_ROWS * 64)
#define PN2  (PN1 + 64 * 17)
#define PB1  (PN2 + 64 * 17)
#define PB2  (PB1 + 64)
#define PREP_FLOATS (PB2 + 64)
#define PREP_BYTES (PREP_FLOATS * 4)

__global__ void __launch_bounds__(256) prep_kernel(
    const int* __restrict__ idx,
    const float* __restrict__ emb1, const float* __restrict__ emb2,
    const float* __restrict__ W1, const float* __restrict__ b1,
    const float* __restrict__ W2, const float* __restrict__ b2)
{
    extern __shared__ float ps[];
    float* W1s  = ps + PW1;
    float* W2s  = ps + PW2;
    float* e1s  = ps + PE1;
    float* e2s  = ps + PE2;
    float* nv1s = ps + PN1;
    float* nv2s = ps + PN2;
    float* b1s  = ps + PB1;
    float* b2s  = ps + PB2;
    __shared__ int gix[PR_ROWS];

    int tid = threadIdx.x;
    int r0  = blockIdx.x * PR_ROWS;

    if (tid < PR_ROWS) gix[tid] = idx[r0 + tid];
    if (tid < 64) { b1s[tid] = b1[tid]; b2s[tid] = b2[tid]; }
    for (int i = tid; i < 64 * 64; i += 256) {
        int o = i >> 6, d = i & 63;
        W1s[o * 65 + d] = W1[i];
        W2s[o * 65 + d] = W2[i];
    }
    __syncthreads();          // gix visible
#pragma unroll
    for (int i = tid; i < PR_ROWS * 64; i += 256) {
        int rb = i >> 6, d = i & 63;
        int g = gix[rb];
        e1s[rb * 64 + d] = emb1[(size_t)g * 64 + d];
        e2s[rb * 64 + d] = emb2[(size_t)g * 64 + d];
    }
    __syncthreads();

    int o   = tid & 63;
    int rbb = tid >> 6;       // 0..3
#pragma unroll
    for (int j = 0; j < 4; j++) {
        int rb = rbb + 4 * j;
        float d1 = 0.f, d2 = 0.f;
#pragma unroll
        for (int d = 0; d < 64; d++) {
            d1 = fmaf(e1s[rb * 64 + d], W1s[o * 65 + d], d1);
            d2 = fmaf(e2s[rb * 64 + d], W2s[o * 65 + d], d2);
        }
        nv1s[o * 17 + rb] = xla_tanh(__fmul_rn(3.0f, __fadd_rn(d1, b1s[o])));
        nv2s[o * 17 + rb] = xla_tanh(__fmul_rn(3.0f, __fadd_rn(d2, b2s[o])));
    }
    __syncthreads();

    // coalesced transposed store-out: 16 consecutive rows per o
#pragma unroll
    for (int i = tid; i < 64 * PR_ROWS; i += 256) {
        int oo = i >> 4, c = i & 15;
        float n1 = nv1s[oo * 17 + c];
        float n2 = nv2s[oo * 17 + c];
        size_t base = (size_t)oo * NROW + r0 + c;
        Ug[base]                        = n1;
        Ug[base + (size_t)64 * NROW]    = n2;
        Vg[base]                        = n2;
        Vg[base + (size_t)64 * NROW]    = -n1;
    }
}

// ---------------- kernel B: stage-1 GEMM (cols 0..255) + top-K ----------------
#define SM_US 0
#define SM_VS 8192
#define SM_CS 16384
#define SM_KV (16384 + 64 * 260)
#define SM_KJ (SM_KV + 64 * 32)
#define SMEM_FLOATS (SM_KJ + 64 * 32)
#define SMEM_BYTES (SMEM_FLOATS * 4)

__global__ void __launch_bounds__(NTHR, 1) stage1_kernel(float* __restrict__ out)
{
    extern __shared__ float sm[];
    float* Us  = sm + SM_US;
    float* Vs  = sm + SM_VS;
    float* Cs  = sm + SM_CS;
    float* kvS = sm + SM_KV;
    int*   kjS = (int*)(sm + SM_KJ);

    int tid = threadIdx.x;
    int r0  = blockIdx.x * BM;

    // zero this block's 64 output rows (overlaps with mainloop)
    {
        float4 z = make_float4(0.f, 0.f, 0.f, 0.f);
        float4* ov = (float4*)(out + (size_t)r0 * NROW);
        for (int i = tid; i < BM * NROW / 4; i += NTHR) ov[i] = z;
    }

    // load resident U tile [128][64]
#pragma unroll
    for (int i = 0; i < 8; i++) {
        int f  = tid + NTHR * i;
        int k  = f >> 4;
        int m4 = (f & 15) << 2;
        *(float4*)&Us[k * 64 + m4] = *(const float4*)&Ug[(size_t)k * NROW + r0 + m4];
    }

    int tx  = tid & 31, ty = tid >> 5;
    int rm0 = ty * 4, rm1 = 32 + ty * 4;
    int cn0 = tx * 4, cn1 = 128 + tx * 4;

    float thv  = 0.f;
    float thaM = 0.f;
    int   cnt  = 0;

    float4 pf0, pf1, pf2, pf3;
    int pk0, pn0, pk1, pn1, pk2, pn2, pk3, pn3;

    {
        int f;
        f = tid;             pk0 = f >> 6; pn0 = (f & 63) << 2;
        f = tid + NTHR;      pk1 = f >> 6; pn1 = (f & 63) << 2;
        f = tid + 2 * NTHR;  pk2 = f >> 6; pn2 = (f & 63) << 2;
        f = tid + 3 * NTHR;  pk3 = f >> 6; pn3 = (f & 63) << 2;
        pf0 = *(const float4*)&Vg[(size_t)pk0 * NROW + pn0];
        pf1 = *(const float4*)&Vg[(size_t)pk1 * NROW + pn1];
        pf2 = *(const float4*)&Vg[(size_t)pk2 * NROW + pn2];
        pf3 = *(const float4*)&Vg[(size_t)pk3 * NROW + pn3];
        *(float4*)&Vs[pk0 * BN + pn0] = pf0;
        *(float4*)&Vs[pk1 * BN + pn1] = pf1;
        *(float4*)&Vs[pk2 * BN + pn2] = pf2;
        *(float4*)&Vs[pk3 * BN + pn3] = pf3;
    }
    __syncthreads();

    int cur = 0;
    for (int jt = 0; jt < NTILES_S1; jt++) {
        float acc[8][8];
#pragma unroll
        for (int i = 0; i < 8; i++)
#pragma unroll
            for (int j = 0; j < 8; j++) acc[i][j] = 0.f;

        for (int kc = 0; kc < NCHUNK; kc++) {
            int g = jt * NCHUNK + kc + 1;
            bool more = (g < NTILES_S1 * NCHUNK);
            if (more) {
                int njt = g >> 3, nkc = g & 7;
                size_t base = (size_t)(nkc * KC) * NROW + njt * BN;
                pf0 = *(const float4*)&Vg[base + (size_t)pk0 * NROW + pn0];
                pf1 = *(const float4*)&Vg[base + (size_t)pk1 * NROW + pn1];
                pf2 = *(const float4*)&Vg[base + (size_t)pk2 * NROW + pn2];
                pf3 = *(const float4*)&Vg[base + (size_t)pk3 * NROW + pn3];
            }
            const float* vb = Vs + cur * (KC * BN);
            const float* ub = Us + kc * KC * 64;
#pragma unroll
            for (int k = 0; k < KC; k++) {
                float4 a0 = *(const float4*)&ub[k * 64 + rm0];
                float4 a1 = *(const float4*)&ub[k * 64 + rm1];
                float4 b0 = *(const float4*)&vb[k * BN + cn0];
                float4 b1 = *(const float4*)&vb[k * BN + cn1];
                float av[8] = {a0.x, a0.y, a0.z, a0.w, a1.x, a1.y, a1.z, a1.w};
                float bv[8] = {b0.x, b0.y, b0.z, b0.w, b1.x, b1.y, b1.z, b1.w};
#pragma unroll
                for (int i = 0; i < 8; i++)
#pragma unroll
                    for (int j = 0; j < 8; j++)
                        acc[i][j] = fmaf(av[i], bv[j], acc[i][j]);
            }
            if (more) {
                float* vw = Vs + (cur ^ 1) * (KC * BN);
                *(float4*)&vw[pk0 * BN + pn0] = pf0;
                *(float4*)&vw[pk1 * BN + pn1] = pf1;
                *(float4*)&vw[pk2 * BN + pn2] = pf2;
                *(float4*)&vw[pk3 * BN + pn3] = pf3;
            }
            __syncthreads();
            cur ^= 1;
        }

        // stage C tile to smem
#pragma unroll
        for (int i = 0; i < 8; i++) {
            int r = (i < 4) ? (rm0 + i) : (rm1 + i - 4);
            *(float4*)&Cs[r * 260 + cn0] = *(float4*)&acc[i][0];
            *(float4*)&Cs[r * 260 + cn1] = *(float4*)&acc[i][4];
        }
        __syncthreads();

        // owner threads scan their row (index-ascending)
        if (tid < 64) {
            int jbase = jt * BN;
            const float* crow = &Cs[tid * 260];
#pragma unroll 4
            for (int c4 = 0; c4 < BN / 4; c4++) {
                float4 q = *(const float4*)&crow[c4 * 4];
                float vals[4] = {q.x, q.y, q.z, q.w};
#pragma unroll
                for (int e = 0; e < 4; e++) {
                    float a = vals[e];
                    if (a <= thaM) continue;
                    float v = xla_tanh(__fmul_rn(3.0f, a));
                    int jidx = jbase + c4 * 4 + e;
                    if (cnt < TOPK) {
                        kvS[tid * TOPK + cnt] = v;
                        kjS[tid * TOPK + cnt] = jidx;
                        cnt++;
                        if (cnt == TOPK) {
                            float mv = kvS[tid * TOPK];
                            for (int s = 1; s < TOPK; s++) mv = fminf(mv, kvS[tid * TOPK + s]);
                            thv = mv;
                        }
                    } else if (v > thv) {
                        int ms = 0; float mv = kvS[tid * TOPK]; int mj = kjS[tid * TOPK];
                        for (int s = 1; s < TOPK; s++) {
                            float sv = kvS[tid * TOPK + s]; int sj = kjS[tid * TOPK + s];
                            if (sv < mv || (sv == mv && sj > mj)) { ms = s; mv = sv; mj = sj; }
                        }
                        kvS[tid * TOPK + ms] = v;
                        kjS[tid * TOPK + ms] = jidx;
                        float nm = kvS[tid * TOPK];
                        for (int s = 1; s < TOPK; s++) nm = fminf(nm, kvS[tid * TOPK + s]);
                        thv = nm;
                    } else {
                        thaM = fmaxf(thaM, a);
                    }
                }
            }
        }
        __syncthreads();
    }

    // finished iff all 32 kept are at the saturated plateau: no later column
    // can evict (strictly-greater required; ties lose by index).
    if (tid < 64) {
        const float vmax = xla_tanh(30.0f);
        int row = r0 + tid;
        bool fin = (cnt == TOPK) && (thv >= vmax);
        g_unf[row] = fin ? 0 : 1;
        if (fin) {
            float* orow = out + (size_t)row * NROW;
            for (int s = 0; s < TOPK; s++) {
                orow[kjS[tid * TOPK + s]] = kvS[tid * TOPK + s];
            }
        }
    }
}

// ---------------- kernel C: fallback — full-row top-K for unfinished rows ----
__global__ void __launch_bounds__(256) fallback_kernel(float* __restrict__ out)
{
    __shared__ float us[KTOT];
    __shared__ float as[256];
    __shared__ float kv[TOPK];
    __shared__ int   kj[TOPK];
    __shared__ float s_thv, s_thaM;
    __shared__ int   s_cnt, s_done;

    int tid = threadIdx.x;
    const float vmax = xla_tanh(30.0f);

    for (int rr = 0; rr < FB_ROWS; rr++) {
        int row = blockIdx.x * FB_ROWS + rr;
        if (g_unf[row] == 0) continue;     // uniform across block

        if (tid < KTOT) us[tid] = Ug[(size_t)tid * NROW + row];
        if (tid == 0) { s_cnt = 0; s_thv = 0.f; s_thaM = 0.f; s_done = 0; }
        __syncthreads();

        for (int jt = 0; jt < NROW / 256; jt++) {
            int j = jt * 256 + tid;
            float acc = 0.f;
#pragma unroll 16
            for (int k = 0; k < KTOT; k++)
                acc = fmaf(us[k], Vg[(size_t)k * NROW + j], acc);
            as[tid] = acc;
            __syncthreads();

            if (tid == 0) {
                int   cnt  = s_cnt;
                float thv  = s_thv;
                float thaM = s_thaM;
                int jbase = jt * 256;
                for (int c = 0; c < 256; c++) {
                    float a = as[c];
                    if (a <= thaM) continue;
                    float v = xla_tanh(__fmul_rn(3.0f, a));
                    int jidx = jbase + c;
                    if (cnt < TOPK) {
                        kv[cnt] = v; kj[cnt] = jidx; cnt++;
                        if (cnt == TOPK) {
                            float mv = kv[0];
                            for (int s = 1; s < TOPK; s++) mv = fminf(mv, kv[s]);
                            thv = mv;
                        }
                    } else if (v > thv) {
                        int ms = 0; float mv = kv[0]; int mj = kj[0];
                        for (int s = 1; s < TOPK; s++) {
                            if (kv[s] < mv || (kv[s] == mv && kj[s] > mj)) { ms = s; mv = kv[s]; mj = kj[s]; }
                        }
                        kv[ms] = v; kj[ms] = jidx;
                        float nm = kv[0];
                        for (int s = 1; s < TOPK; s++) nm = fminf(nm, kv[s]);
                        thv = nm;
                    } else {
                        thaM = fmaxf(thaM, a);
                    }
                }
                s_cnt = cnt; s_thv = thv; s_thaM = thaM;
                if (cnt == TOPK && thv >= vmax) s_done = 1;
            }
            __syncthreads();
            if (s_done) break;
        }

        if (tid == 0) {
            float* orow = out + (size_t)row * NROW;
            for (int s = 0; s < s_cnt; s++) orow[kj[s]] = kv[s];
        }
        __syncthreads();
    }
}

extern "C" void kernel_launch(void* const* d_in, const int* in_sizes, int n_in,
                              void* d_out, int out_size)
{
    const int*   idx  = (const int*)d_in[0];
    const float* emb1 = (const float*)d_in[1];
    const float* emb2 = (const float*)d_in[2];
    const float* W1   = (const float*)d_in[3];
    const float* b1   = (const float*)d_in[4];
    const float* W2   = (const float*)d_in[5];
    const float* b2   = (const float*)d_in[6];
    float* out = (float*)d_out;

    static bool configured = false;
    if (!configured) {
        cudaFuncSetAttribute(stage1_kernel, cudaFuncAttributeMaxDynamicSharedMemorySize, SMEM_BYTES);
        cudaFuncSetAttribute(prep_kernel, cudaFuncAttributeMaxDynamicSharedMemorySize, PREP_BYTES);
        configured = true;
    }

    prep_kernel<<<NROW / PR_ROWS, 256, PREP_BYTES>>>(idx, emb1, emb2, W1, b1, W2, b2);
    stage1_kernel<<<NROW / BM, NTHR, SMEM_BYTES>>>(out);
    fallback_kernel<<<NROW / FB_ROWS, 256>>>(out);
}